// round 13
// baseline (speedup 1.0000x reference)
#include <cuda_runtime.h>
#include <cuda_fp16.h>
#include <cstdint>

#define NN 20000
#define DD 32
#define HH 64

typedef unsigned long long ull;

// ---------------- scratch (static device globals; no allocation) ----------------
__device__ int   g_nbr_sorted[NN * DD];
__device__ float g_Xg[(size_t)NN * 256];     // pair-interleaved: col = 16*(u/4)+8*(g/2)+2*(u%4)+(g%1?0:0)
__device__ float g_hA[(size_t)NN * HH];
__device__ float g_hB[(size_t)NN * HH];
__device__ float g_agg[(size_t)NN * HH];

// gate/unit -> Xg column permutation
__device__ __forceinline__ int gcol(int u, int g) {
    return 16 * (u >> 2) + 8 * (g >> 1) + 2 * (u & 3) + (g & 1);
}

// ---------------- helpers ----------------
__device__ __forceinline__ uint32_t smem_u32(const void* p) {
    uint32_t a;
    asm("{ .reg .u64 t; cvta.to.shared.u64 t, %1; cvt.u32.u64 %0, t; }" : "=r"(a) : "l"(p));
    return a;
}
__device__ __forceinline__ float tanha(float x) {
    float r; asm("tanh.approx.f32 %0, %1;" : "=f"(r) : "f"(x)); return r;
}
__device__ __forceinline__ float sigta(float x) { return fmaf(tanha(0.5f * x), 0.5f, 0.5f); }

__device__ __forceinline__ void ldsm4(uint32_t* r, uint32_t a) {
    asm volatile("ldmatrix.sync.aligned.m8n8.x4.shared.b16 {%0,%1,%2,%3}, [%4];"
        : "=r"(r[0]), "=r"(r[1]), "=r"(r[2]), "=r"(r[3]) : "r"(a));
}
__device__ __forceinline__ void ldsm2(uint32_t* r, uint32_t a) {
    asm volatile("ldmatrix.sync.aligned.m8n8.x2.shared.b16 {%0,%1}, [%2];"
        : "=r"(r[0]), "=r"(r[1]) : "r"(a));
}
__device__ __forceinline__ void mma_f16(float* d, const uint32_t* a, const uint32_t* b) {
    asm volatile("mma.sync.aligned.m16n8k16.row.col.f32.f16.f16.f32 "
        "{%0,%1,%2,%3}, {%4,%5,%6,%7}, {%8,%9}, {%0,%1,%2,%3};"
        : "+f"(d[0]), "+f"(d[1]), "+f"(d[2]), "+f"(d[3])
        : "r"(a[0]), "r"(a[1]), "r"(a[2]), "r"(a[3]), "r"(b[0]), "r"(b[1]));
}

// ---------------- neighbor sort ----------------
__global__ void sort_kernel(const int* __restrict__ nbr) {
    int gw = (blockIdx.x * blockDim.x + threadIdx.x) >> 5;
    int lane = threadIdx.x & 31;
    if (gw >= NN) return;
    int v = nbr[gw * DD + lane];
#pragma unroll
    for (int k = 2; k <= 32; k <<= 1) {
#pragma unroll
        for (int j = k >> 1; j > 0; j >>= 1) {
            int p = __shfl_xor_sync(0xFFFFFFFFu, v, j);
            bool up = ((lane & k) == 0);
            bool lo = ((lane & j) == 0);
            int mn = min(v, p), mx = max(v, p);
            v = (up == lo) ? mn : mx;
        }
    }
    g_nbr_sorted[gw * DD + lane] = v;
}

// ---------------- standalone proj for layer 0 (IN_D = 3) ----------------
#define PROJ_SMEM ((64 * 257 + 64 * 64) * 4)
template <int IN_D>
__global__ void proj_kernel(const float* __restrict__ h_in, const float* __restrict__ W_ih,
                            const float* __restrict__ b_ih, const float* __restrict__ b_hh) {
    extern __shared__ float sm[];
    float* sWT = sm;
    float* sh  = sm + 64 * 257;
    int tid = threadIdx.x;
    for (int i = tid; i < IN_D * 256; i += 256) {
        int j = i / IN_D, k = i - j * IN_D;
        sWT[k * 257 + j] = W_ih[i];
    }
    int base = blockIdx.x * 64;
    for (int i = tid; i < 64 * IN_D; i += 256) {
        int m = i / IN_D;
        int node = min(base + m, NN - 1);
        sh[i] = h_in[(size_t)node * IN_D + (i - m * IN_D)];
    }
    float bias = b_ih[tid] + b_hh[tid];
    int dst = gcol(tid & 63, tid >> 6);
    __syncthreads();
#pragma unroll
    for (int mb = 0; mb < 64; mb += 8) {
        float acc[8];
#pragma unroll
        for (int mm = 0; mm < 8; mm++) acc[mm] = bias;
#pragma unroll
        for (int k = 0; k < IN_D; k++) {
            float wv = sWT[k * 257 + tid];
#pragma unroll
            for (int mm = 0; mm < 8; mm++)
                acc[mm] = fmaf(sh[(mb + mm) * IN_D + k], wv, acc[mm]);
        }
#pragma unroll
        for (int mm = 0; mm < 8; mm++) {
            int node = base + mb + mm;
            if (node < NN) g_Xg[(size_t)node * 256 + dst] = acc[mm];
        }
    }
}

// ---------------- HMMA LSTM recurrence (fp16, no-shfl gate layout, 3 CTAs/SM) ----------------
#define M_TILES 3
#define NPC 44
#define A_ROWS 48
#define AST 72
#define OFF_B 0
#define OFF_A (256 * AST * 2)                    // 36864
#define ABUF  (A_ROWS * AST * 2)                 // 6912
#define LSTM_SMEM (OFF_A + 2 * ABUF)             // 50688

__global__ __launch_bounds__(128, 3) void lstm_mma_kernel(const float* __restrict__ W_hh) {
    extern __shared__ char smem[];
    uint32_t sb = smem_u32(smem);
    int tid = threadIdx.x, lane = tid & 31, w = tid >> 5;
    int q = lane & 3, rh = lane >> 2;

    for (int i = tid; i < 256 * 64; i += 128) {
        int r = i >> 6, k = i & 63;
        int col = gcol(r & 63, r >> 6);
        ((__half*)(smem + OFF_B))[col * AST + k] = __float2half_rn(W_hh[i]);
    }
    __syncthreads();

    int base = blockIdx.x * NPC;
    float c[M_TILES * 8];
#pragma unroll
    for (int i = 0; i < M_TILES * 8; i++) c[i] = 0.f;

    uint32_t aoff = (uint32_t)(((lane & 15) * AST + (lane >> 4) * 8) * 2);
    uint32_t boff = (uint32_t)(((w * 64 + (lane & 7)) * AST + ((lane >> 3) & 1) * 8) * 2);

    int rowL[M_TILES], rowH[M_TILES];
#pragma unroll
    for (int mi = 0; mi < M_TILES; mi++) {
        rowL[mi] = min(base + mi * 16 + rh, NN - 1) * DD;
        rowH[mi] = min(base + mi * 16 + rh + 8, NN - 1) * DD;
    }

    int idxL[M_TILES], idxH[M_TILES];
#pragma unroll
    for (int mi = 0; mi < M_TILES; mi++) {
        idxL[mi] = g_nbr_sorted[rowL[mi]];
        idxH[mi] = g_nbr_sorted[rowH[mi]];
    }

    for (int t = 0; t < DD; t++) {
        if (t) __syncthreads();
        int rb = (t - 1) & 1;
        int wb = t & 1;

        int tn = (t + 1) & 31;
        int idxLn[M_TILES], idxHn[M_TILES];
#pragma unroll
        for (int mi = 0; mi < M_TILES; mi++) {
            idxLn[mi] = g_nbr_sorted[rowL[mi] + tn];
            idxHn[mi] = g_nbr_sorted[rowH[mi] + tn];
        }

#pragma unroll
        for (int nb = 0; nb < 2; nb++) {
            float2 xg[2][4][2];
#pragma unroll
            for (int nj = 0; nj < 4; nj++) {
                int col = w * 64 + (nb * 4 + nj) * 8 + 2 * q;
                xg[0][nj][0] = __ldg((const float2*)(g_Xg + (size_t)idxL[0] * 256 + col));
                xg[0][nj][1] = __ldg((const float2*)(g_Xg + (size_t)idxH[0] * 256 + col));
            }

            float d[M_TILES][4][4];
#pragma unroll
            for (int mi = 0; mi < M_TILES; mi++)
#pragma unroll
                for (int nj = 0; nj < 4; nj++)
#pragma unroll
                    for (int e = 0; e < 4; e++) d[mi][nj][e] = 0.f;

            if (t) {
                uint32_t aB = sb + OFF_A + (uint32_t)rb * ABUF + aoff;
#pragma unroll
                for (int kc = 0; kc < 4; kc++) {
                    uint32_t ah[M_TILES][4];
#pragma unroll
                    for (int mi = 0; mi < M_TILES; mi++)
                        ldsm4(ah[mi], aB + (uint32_t)((mi * 16 * AST + kc * 16) * 2));
#pragma unroll
                    for (int nj = 0; nj < 4; nj++) {
                        uint32_t bh[2];
                        ldsm2(bh, sb + OFF_B + boff + (uint32_t)((((nb * 4 + nj) * 8) * AST + kc * 16) * 2));
#pragma unroll
                        for (int mi = 0; mi < M_TILES; mi++) mma_f16(d[mi][nj], ah[mi], bh);
                    }
                }
            }

            __half* sA = (__half*)(smem + OFF_A + (size_t)wb * ABUF);
#pragma unroll
            for (int mi = 0; mi < M_TILES; mi++) {
                if (mi + 1 < M_TILES) {
#pragma unroll
                    for (int nj = 0; nj < 4; nj++) {
                        int col = w * 64 + (nb * 4 + nj) * 8 + 2 * q;
                        xg[(mi + 1) & 1][nj][0] = __ldg((const float2*)(g_Xg + (size_t)idxL[mi + 1] * 256 + col));
                        xg[(mi + 1) & 1][nj][1] = __ldg((const float2*)(g_Xg + (size_t)idxH[mi + 1] * 256 + col));
                    }
                }
#pragma unroll
                for (int pp = 0; pp < 2; pp++) {
                    int njA = 2 * pp, njB = 2 * pp + 1;
                    float2 xLA = xg[mi & 1][njA][0], xHA = xg[mi & 1][njA][1];
                    float2 xLB = xg[mi & 1][njB][0], xHB = xg[mi & 1][njB][1];
                    float I_L = d[mi][njA][0] + xLA.x, F_L = d[mi][njA][1] + xLA.y;
                    float G_L = d[mi][njB][0] + xLB.x, O_L = d[mi][njB][1] + xLB.y;
                    float I_H = d[mi][njA][2] + xHA.x, F_H = d[mi][njA][3] + xHA.y;
                    float G_H = d[mi][njB][2] + xHB.x, O_H = d[mi][njB][3] + xHB.y;
                    int ci = mi * 8 + nb * 4 + pp * 2;
                    float cL = fmaf(sigta(F_L), c[ci], sigta(I_L) * tanha(G_L));
                    c[ci] = cL;
                    float hL = sigta(O_L) * tanha(cL);
                    float cH = fmaf(sigta(F_H), c[ci + 1], sigta(I_H) * tanha(G_H));
                    c[ci + 1] = cH;
                    float hH = sigta(O_H) * tanha(cH);
                    int u = w * 16 + (nb * 2 + pp) * 4 + q;
                    int rL = mi * 16 + rh, rH = rL + 8;
                    sA[rL * AST + u] = __float2half_rn(hL);
                    sA[rH * AST + u] = __float2half_rn(hH);
                    if (t == DD - 1) {
                        int nodeL = base + rL, nodeH = base + rH;
                        if (rL < NPC && nodeL < NN) g_agg[(size_t)nodeL * 64 + u] = hL;
                        if (rH < NPC && nodeH < NN) g_agg[(size_t)nodeH * 64 + u] = hH;
                    }
                }
            }
        }
#pragma unroll
        for (int mi = 0; mi < M_TILES; mi++) { idxL[mi] = idxLn[mi]; idxH[mi] = idxHn[mi]; }
    }
}

// ---------------- fused combine (+ next-layer proj), 512 threads, 3 syncs ----------------
// DO_PROJ layout (floats):
//   [0, 16640)            : GEMM1 sWT[K][65] + scomb[64][K] -> later overlaid by W2[256][65]
//   [16640, 16640+64*68)  : hbuf[64][68] (separate region, never overlaps)
// non-proj: hbuf unused, no writes into it.
#define R0_FLOATS (256 * 65)                       // 16640
#define FUSE_SMEM   ((R0_FLOATS + 64 * 68) * 4)    // 83968 B (DO_PROJ)
#define FUSE_SMEM_NP ((128 * 65 + 64 * 128) * 4)   // 66048 B (no proj)

template <int IN_D, bool DO_PROJ>
__global__ __launch_bounds__(512, 2) void fused_combine(
        const float* __restrict__ h_in, const float* __restrict__ Wl,
        const float* __restrict__ bl, float* __restrict__ h_out,
        const float* __restrict__ W_ihn, const float* __restrict__ b_ihn,
        const float* __restrict__ b_hhn) {
    constexpr int K = IN_D + 64;
    extern __shared__ float csm[];
    float* sWT   = csm;                    // [K][65]
    float* scomb = csm + K * 65;           // [64][K]
    float* hbuf  = csm + R0_FLOATS;        // [64][68], only used when DO_PROJ
    int tid = threadIdx.x;

    // stage Wl^T and [h_in, agg]
    for (int i = tid; i < 64 * K; i += 512) {
        int j = i / K, k = i - j * K;
        sWT[k * 65 + j] = Wl[i];
    }
    int base = blockIdx.x * 64;
    for (int i = tid; i < 64 * IN_D; i += 512) {
        int m = i / IN_D;
        int node = min(base + m, NN - 1);
        scomb[m * K + (i - m * IN_D)] = h_in[(size_t)node * IN_D + (i - m * IN_D)];
    }
    for (int i = tid; i < 64 * 64; i += 512) {
        int m = i >> 6;
        int node = min(base + m, NN - 1);
        scomb[m * K + IN_D + (i & 63)] = g_agg[(size_t)node * 64 + (i & 63)];
    }
    __syncthreads();

    // GEMM1: 512 threads, j = out col, 8 m per thread
    {
        int j = tid & 63, mg = tid >> 6;   // mg 0..7
        float acc[8];
        float bj = bl[j];
#pragma unroll
        for (int mm = 0; mm < 8; mm++) acc[mm] = bj;
        if (IN_D == 64) {
            for (int k0 = 0; k0 < 128; k0 += 4) {
                float w0 = sWT[(k0 + 0) * 65 + j];
                float w1 = sWT[(k0 + 1) * 65 + j];
                float w2 = sWT[(k0 + 2) * 65 + j];
                float w3 = sWT[(k0 + 3) * 65 + j];
#pragma unroll
                for (int mm = 0; mm < 8; mm++) {
                    float4 s = *(const float4*)&scomb[(mg * 8 + mm) * 128 + k0];
                    acc[mm] = fmaf(s.x, w0, acc[mm]);
                    acc[mm] = fmaf(s.y, w1, acc[mm]);
                    acc[mm] = fmaf(s.z, w2, acc[mm]);
                    acc[mm] = fmaf(s.w, w3, acc[mm]);
                }
            }
        } else {
            for (int k = 0; k < K; k++) {
                float wv = sWT[k * 65 + j];
#pragma unroll
                for (int mm = 0; mm < 8; mm++)
                    acc[mm] = fmaf(scomb[(mg * 8 + mm) * K + k], wv, acc[mm]);
            }
        }
#pragma unroll
        for (int mm = 0; mm < 8; mm++) {
            int m = mg * 8 + mm;
            float v = fmaxf(acc[mm], 0.f);
            if (DO_PROJ) hbuf[m * 68 + j] = v;   // distinct region when DO_PROJ; skipped otherwise
            int node = base + m;
            if (node < NN) h_out[(size_t)node * 64 + j] = v;
        }
    }
    if (DO_PROJ) {
        __syncthreads();   // all reads of sWT/scomb complete

        // stage full W_ihn as W2[256][65] over the GEMM1 region
        float* W2 = csm;
        for (int i = tid; i < 256 * 64; i += 512)
            W2[(i >> 6) * 65 + (i & 63)] = W_ihn[i];
        __syncthreads();

        // GEMM2: thread = (weight row r, m-half), two passes of 16 m
        int r = tid & 255;                 // 0..255
        int mh = tid >> 8;                 // 0..1 -> 32 m each
        int dst = gcol(r & 63, r >> 6);
        float bias = b_ihn[r] + b_hhn[r];
#pragma unroll
        for (int half = 0; half < 2; half++) {
            int m0 = mh * 32 + half * 16;
            float pacc[16];
#pragma unroll
            for (int mm = 0; mm < 16; mm++) pacc[mm] = bias;
            for (int k0 = 0; k0 < 64; k0 += 4) {
                float w0 = W2[r * 65 + k0 + 0];
                float w1 = W2[r * 65 + k0 + 1];
                float w2 = W2[r * 65 + k0 + 2];
                float w3 = W2[r * 65 + k0 + 3];
#pragma unroll
                for (int mm = 0; mm < 16; mm++) {
                    float4 h4 = *(const float4*)&hbuf[(m0 + mm) * 68 + k0];
                    pacc[mm] = fmaf(h4.x, w0, pacc[mm]);
                    pacc[mm] = fmaf(h4.y, w1, pacc[mm]);
                    pacc[mm] = fmaf(h4.z, w2, pacc[mm]);
                    pacc[mm] = fmaf(h4.w, w3, pacc[mm]);
                }
            }
#pragma unroll
            for (int mm = 0; mm < 16; mm++) {
                int node = base + m0 + mm;
                if (node < NN) g_Xg[(size_t)node * 256 + dst] = pacc[mm];
            }
        }
    }
}

// ---------------- output head ----------------
__global__ void out_kernel(const float* __restrict__ h, const float* __restrict__ W_out,
                           const float* __restrict__ b_out, float* __restrict__ out) {
    int gw = (blockIdx.x * blockDim.x + threadIdx.x) >> 5;
    int lane = threadIdx.x & 31;
    if (gw >= NN) return;
    float2 hv = *(const float2*)(h + (size_t)gw * 64 + 2 * lane);
    float2 wv = *(const float2*)(W_out + 2 * lane);
    float s = hv.x * wv.x + hv.y * wv.y;
#pragma unroll
    for (int o = 16; o; o >>= 1) s += __shfl_xor_sync(0xFFFFFFFFu, s, o);
    if (lane == 0) out[gw] = s + b_out[0];
}

// ---------------- launch ----------------
extern "C" void kernel_launch(void* const* d_in, const int* in_sizes, int n_in,
                              void* d_out, int out_size) {
    (void)in_sizes; (void)n_in; (void)out_size;
    const float* nf   = (const float*)d_in[0];
    const int*   nbr  = (const int*)d_in[1];
    const float* Wout = (const float*)d_in[20];
    const float* bout = (const float*)d_in[21];
    float* out = (float*)d_out;

    float *hA = nullptr, *hB = nullptr;
    cudaGetSymbolAddress((void**)&hA, g_hA);
    cudaGetSymbolAddress((void**)&hB, g_hB);

    cudaFuncSetAttribute(lstm_mma_kernel, cudaFuncAttributeMaxDynamicSharedMemorySize, LSTM_SMEM);
    cudaFuncSetAttribute(proj_kernel<3>,  cudaFuncAttributeMaxDynamicSharedMemorySize, PROJ_SMEM);
    cudaFuncSetAttribute(fused_combine<3, true>,   cudaFuncAttributeMaxDynamicSharedMemorySize, FUSE_SMEM);
    cudaFuncSetAttribute(fused_combine<64, true>,  cudaFuncAttributeMaxDynamicSharedMemorySize, FUSE_SMEM);
    cudaFuncSetAttribute(fused_combine<64, false>, cudaFuncAttributeMaxDynamicSharedMemorySize, FUSE_SMEM_NP);

    const float* W_hh0 = (const float*)d_in[3];
    const float* Wl0   = (const float*)d_in[6];
    const float* bl0   = (const float*)d_in[7];
    const float* W_ih1 = (const float*)d_in[8];
    const float* W_hh1 = (const float*)d_in[9];
    const float* b_ih1 = (const float*)d_in[10];
    const float* b_hh1 = (const float*)d_in[11];
    const float* Wl1   = (const float*)d_in[12];
    const float* bl1   = (const float*)d_in[13];
    const float* W_ih2 = (const float*)d_in[14];
    const float* W_hh2 = (const float*)d_in[15];
    const float* b_ih2 = (const float*)d_in[16];
    const float* b_hh2 = (const float*)d_in[17];
    const float* Wl2   = (const float*)d_in[18];
    const float* bl2   = (const float*)d_in[19];

    int lstm_grid = (NN + NPC - 1) / NPC;   // 455 <= 456 = 152*3
    int blk64 = (NN + 63) / 64;             // 313

    sort_kernel<<<NN / 8, 256>>>(nbr);

    // layer 0
    proj_kernel<3><<<blk64, 256, PROJ_SMEM>>>(nf, (const float*)d_in[2],
                                              (const float*)d_in[4], (const float*)d_in[5]);
    lstm_mma_kernel<<<lstm_grid, 128, LSTM_SMEM>>>(W_hh0);
    fused_combine<3, true><<<blk64, 512, FUSE_SMEM>>>(nf, Wl0, bl0, hA, W_ih1, b_ih1, b_hh1);
    // layer 1
    lstm_mma_kernel<<<lstm_grid, 128, LSTM_SMEM>>>(W_hh1);
    fused_combine<64, true><<<blk64, 512, FUSE_SMEM>>>(hA, Wl1, bl1, hB, W_ih2, b_ih2, b_hh2);
    // layer 2
    lstm_mma_kernel<<<lstm_grid, 128, LSTM_SMEM>>>(W_hh2);
    fused_combine<64, false><<<blk64, 512, FUSE_SMEM_NP>>>(hB, Wl2, bl2, hA, nullptr, nullptr, nullptr);

    out_kernel<<<NN / 8, 256>>>(hA, Wout, bout, out);
}

// round 14
// speedup vs baseline: 1.0709x; 1.0709x over previous
#include <cuda_runtime.h>
#include <cuda_fp16.h>
#include <cstdint>

#define NN 20000
#define DD 32
#define HH 64

typedef unsigned long long ull;

// ---------------- scratch (static device globals; no allocation) ----------------
__device__ int   g_nbr_sorted[NN * DD];
__device__ float g_Xg[(size_t)NN * 256];     // pair-interleaved columns (see gcol)
__device__ float g_hA[(size_t)NN * HH];
__device__ float g_hB[(size_t)NN * HH];
__device__ float g_agg[(size_t)NN * HH];

// gate/unit -> Xg column permutation
__device__ __forceinline__ int gcol(int u, int g) {
    return 16 * (u >> 2) + 8 * (g >> 1) + 2 * (u & 3) + (g & 1);
}

// ---------------- helpers ----------------
__device__ __forceinline__ uint32_t smem_u32(const void* p) {
    uint32_t a;
    asm("{ .reg .u64 t; cvta.to.shared.u64 t, %1; cvt.u32.u64 %0, t; }" : "=r"(a) : "l"(p));
    return a;
}
__device__ __forceinline__ float tanha(float x) {
    float r; asm("tanh.approx.f32 %0, %1;" : "=f"(r) : "f"(x)); return r;
}
__device__ __forceinline__ float sigta(float x) { return fmaf(tanha(0.5f * x), 0.5f, 0.5f); }

__device__ __forceinline__ void ldsm4(uint32_t* r, uint32_t a) {
    asm volatile("ldmatrix.sync.aligned.m8n8.x4.shared.b16 {%0,%1,%2,%3}, [%4];"
        : "=r"(r[0]), "=r"(r[1]), "=r"(r[2]), "=r"(r[3]) : "r"(a));
}
__device__ __forceinline__ void ldsm2(uint32_t* r, uint32_t a) {
    asm volatile("ldmatrix.sync.aligned.m8n8.x2.shared.b16 {%0,%1}, [%2];"
        : "=r"(r[0]), "=r"(r[1]) : "r"(a));
}
__device__ __forceinline__ void mma_f16(float* d, const uint32_t* a, const uint32_t* b) {
    asm volatile("mma.sync.aligned.m16n8k16.row.col.f32.f16.f16.f32 "
        "{%0,%1,%2,%3}, {%4,%5,%6,%7}, {%8,%9}, {%0,%1,%2,%3};"
        : "+f"(d[0]), "+f"(d[1]), "+f"(d[2]), "+f"(d[3])
        : "r"(a[0]), "r"(a[1]), "r"(a[2]), "r"(a[3]), "r"(b[0]), "r"(b[1]));
}

// ---------------- neighbor sort ----------------
__global__ void sort_kernel(const int* __restrict__ nbr) {
    int gw = (blockIdx.x * blockDim.x + threadIdx.x) >> 5;
    int lane = threadIdx.x & 31;
    if (gw >= NN) return;
    int v = nbr[gw * DD + lane];
#pragma unroll
    for (int k = 2; k <= 32; k <<= 1) {
#pragma unroll
        for (int j = k >> 1; j > 0; j >>= 1) {
            int p = __shfl_xor_sync(0xFFFFFFFFu, v, j);
            bool up = ((lane & k) == 0);
            bool lo = ((lane & j) == 0);
            int mn = min(v, p), mx = max(v, p);
            v = (up == lo) ? mn : mx;
        }
    }
    g_nbr_sorted[gw * DD + lane] = v;
}

// ---------------- standalone proj for layer 0 (IN_D = 3) ----------------
#define PROJ_SMEM ((64 * 257 + 64 * 64) * 4)
template <int IN_D>
__global__ void proj_kernel(const float* __restrict__ h_in, const float* __restrict__ W_ih,
                            const float* __restrict__ b_ih, const float* __restrict__ b_hh) {
    extern __shared__ float sm[];
    float* sWT = sm;
    float* sh  = sm + 64 * 257;
    int tid = threadIdx.x;
    for (int i = tid; i < IN_D * 256; i += 256) {
        int j = i / IN_D, k = i - j * IN_D;
        sWT[k * 257 + j] = W_ih[i];
    }
    int base = blockIdx.x * 64;
    for (int i = tid; i < 64 * IN_D; i += 256) {
        int m = i / IN_D;
        int node = min(base + m, NN - 1);
        sh[i] = h_in[(size_t)node * IN_D + (i - m * IN_D)];
    }
    float bias = b_ih[tid] + b_hh[tid];
    int dst = gcol(tid & 63, tid >> 6);
    __syncthreads();
#pragma unroll
    for (int mb = 0; mb < 64; mb += 8) {
        float acc[8];
#pragma unroll
        for (int mm = 0; mm < 8; mm++) acc[mm] = bias;
#pragma unroll
        for (int k = 0; k < IN_D; k++) {
            float wv = sWT[k * 257 + tid];
#pragma unroll
            for (int mm = 0; mm < 8; mm++)
                acc[mm] = fmaf(sh[(mb + mm) * IN_D + k], wv, acc[mm]);
        }
#pragma unroll
        for (int mm = 0; mm < 8; mm++) {
            int node = base + mb + mm;
            if (node < NN) g_Xg[(size_t)node * 256 + dst] = acc[mm];
        }
    }
}

// ---------------- HMMA LSTM recurrence (fp16, no-shfl gate layout, 3 CTAs/SM) ----------------
#define M_TILES 3
#define NPC 44
#define A_ROWS 48
#define AST 72
#define OFF_B 0
#define OFF_A (256 * AST * 2)                    // 36864
#define ABUF  (A_ROWS * AST * 2)                 // 6912
#define LSTM_SMEM (OFF_A + 2 * ABUF)             // 50688

__global__ __launch_bounds__(128, 3) void lstm_mma_kernel(const float* __restrict__ W_hh) {
    extern __shared__ char smem[];
    uint32_t sb = smem_u32(smem);
    int tid = threadIdx.x, lane = tid & 31, w = tid >> 5;
    int q = lane & 3, rh = lane >> 2;

    for (int i = tid; i < 256 * 64; i += 128) {
        int r = i >> 6, k = i & 63;
        int col = gcol(r & 63, r >> 6);
        ((__half*)(smem + OFF_B))[col * AST + k] = __float2half_rn(W_hh[i]);
    }
    __syncthreads();

    int base = blockIdx.x * NPC;
    float c[M_TILES * 8];
#pragma unroll
    for (int i = 0; i < M_TILES * 8; i++) c[i] = 0.f;

    uint32_t aoff = (uint32_t)(((lane & 15) * AST + (lane >> 4) * 8) * 2);
    uint32_t boff = (uint32_t)(((w * 64 + (lane & 7)) * AST + ((lane >> 3) & 1) * 8) * 2);

    int rowL[M_TILES], rowH[M_TILES];
#pragma unroll
    for (int mi = 0; mi < M_TILES; mi++) {
        rowL[mi] = min(base + mi * 16 + rh, NN - 1) * DD;
        rowH[mi] = min(base + mi * 16 + rh + 8, NN - 1) * DD;
    }

    int idxL[M_TILES], idxH[M_TILES];
#pragma unroll
    for (int mi = 0; mi < M_TILES; mi++) {
        idxL[mi] = g_nbr_sorted[rowL[mi]];
        idxH[mi] = g_nbr_sorted[rowH[mi]];
    }

    for (int t = 0; t < DD; t++) {
        if (t) __syncthreads();
        int rb = (t - 1) & 1;
        int wb = t & 1;

        int tn = (t + 1) & 31;
        int idxLn[M_TILES], idxHn[M_TILES];
#pragma unroll
        for (int mi = 0; mi < M_TILES; mi++) {
            idxLn[mi] = g_nbr_sorted[rowL[mi] + tn];
            idxHn[mi] = g_nbr_sorted[rowH[mi] + tn];
        }

#pragma unroll
        for (int nb = 0; nb < 2; nb++) {
            float2 xg[2][4][2];
#pragma unroll
            for (int nj = 0; nj < 4; nj++) {
                int col = w * 64 + (nb * 4 + nj) * 8 + 2 * q;
                xg[0][nj][0] = __ldg((const float2*)(g_Xg + (size_t)idxL[0] * 256 + col));
                xg[0][nj][1] = __ldg((const float2*)(g_Xg + (size_t)idxH[0] * 256 + col));
            }

            float d[M_TILES][4][4];
#pragma unroll
            for (int mi = 0; mi < M_TILES; mi++)
#pragma unroll
                for (int nj = 0; nj < 4; nj++)
#pragma unroll
                    for (int e = 0; e < 4; e++) d[mi][nj][e] = 0.f;

            if (t) {
                uint32_t aB = sb + OFF_A + (uint32_t)rb * ABUF + aoff;
#pragma unroll
                for (int kc = 0; kc < 4; kc++) {
                    uint32_t ah[M_TILES][4];
#pragma unroll
                    for (int mi = 0; mi < M_TILES; mi++)
                        ldsm4(ah[mi], aB + (uint32_t)((mi * 16 * AST + kc * 16) * 2));
#pragma unroll
                    for (int nj = 0; nj < 4; nj++) {
                        uint32_t bh[2];
                        ldsm2(bh, sb + OFF_B + boff + (uint32_t)((((nb * 4 + nj) * 8) * AST + kc * 16) * 2));
#pragma unroll
                        for (int mi = 0; mi < M_TILES; mi++) mma_f16(d[mi][nj], ah[mi], bh);
                    }
                }
            }

            __half* sA = (__half*)(smem + OFF_A + (size_t)wb * ABUF);
#pragma unroll
            for (int mi = 0; mi < M_TILES; mi++) {
                if (mi + 1 < M_TILES) {
#pragma unroll
                    for (int nj = 0; nj < 4; nj++) {
                        int col = w * 64 + (nb * 4 + nj) * 8 + 2 * q;
                        xg[(mi + 1) & 1][nj][0] = __ldg((const float2*)(g_Xg + (size_t)idxL[mi + 1] * 256 + col));
                        xg[(mi + 1) & 1][nj][1] = __ldg((const float2*)(g_Xg + (size_t)idxH[mi + 1] * 256 + col));
                    }
                }
#pragma unroll
                for (int pp = 0; pp < 2; pp++) {
                    int njA = 2 * pp, njB = 2 * pp + 1;
                    float2 xLA = xg[mi & 1][njA][0], xHA = xg[mi & 1][njA][1];
                    float2 xLB = xg[mi & 1][njB][0], xHB = xg[mi & 1][njB][1];
                    float I_L = d[mi][njA][0] + xLA.x, F_L = d[mi][njA][1] + xLA.y;
                    float G_L = d[mi][njB][0] + xLB.x, O_L = d[mi][njB][1] + xLB.y;
                    float I_H = d[mi][njA][2] + xHA.x, F_H = d[mi][njA][3] + xHA.y;
                    float G_H = d[mi][njB][2] + xHB.x, O_H = d[mi][njB][3] + xHB.y;
                    int ci = mi * 8 + nb * 4 + pp * 2;
                    float cL = fmaf(sigta(F_L), c[ci], sigta(I_L) * tanha(G_L));
                    c[ci] = cL;
                    float hL = sigta(O_L) * tanha(cL);
                    float cH = fmaf(sigta(F_H), c[ci + 1], sigta(I_H) * tanha(G_H));
                    c[ci + 1] = cH;
                    float hH = sigta(O_H) * tanha(cH);
                    int u = w * 16 + (nb * 2 + pp) * 4 + q;
                    int rL = mi * 16 + rh, rH = rL + 8;
                    sA[rL * AST + u] = __float2half_rn(hL);
                    sA[rH * AST + u] = __float2half_rn(hH);
                    if (t == DD - 1) {
                        int nodeL = base + rL, nodeH = base + rH;
                        if (rL < NPC && nodeL < NN) g_agg[(size_t)nodeL * 64 + u] = hL;
                        if (rH < NPC && nodeH < NN) g_agg[(size_t)nodeH * 64 + u] = hH;
                    }
                }
            }
        }
#pragma unroll
        for (int mi = 0; mi < M_TILES; mi++) { idxL[mi] = idxLn[mi]; idxH[mi] = idxHn[mi]; }
    }
}

// ---------------- fused combine (+ next-layer proj): ONE WAVE (grid 304, 66 nodes/CTA) ----------------
// Region layout (floats):
//   [0, R0)          : GEMM1 sWT[K][65] + scomb[66][K]  -> later overlaid by W2[256][65]
//   [R0, R0+66*68)   : hbuf[66][68]  (separate region; only used when DO_PROJ)
#define FC_NPC 66
#define FC_GRID 304                                 // 304*66 = 20064 >= 20000; == 152 SMs * 2 CTAs
#define R0_FLOATS (128 * 65 + 66 * 128)             // 16768 (covers 256*65=16640 for W2 too)
#define FUSE_SMEM    ((R0_FLOATS + 66 * 68) * 4)    // 85024 B (DO_PROJ)
#define FUSE_SMEM_NP (R0_FLOATS * 4)                // 67072 B (no proj)

template <int IN_D, bool DO_PROJ>
__global__ __launch_bounds__(512, 2) void fused_combine(
        const float* __restrict__ h_in, const float* __restrict__ Wl,
        const float* __restrict__ bl, float* __restrict__ h_out,
        const float* __restrict__ W_ihn, const float* __restrict__ b_ihn,
        const float* __restrict__ b_hhn) {
    constexpr int K = IN_D + 64;
    extern __shared__ float csm[];
    float* sWT   = csm;                    // [K][65]
    float* scomb = csm + K * 65;           // [66][K]
    float* hbuf  = csm + R0_FLOATS;        // [66][68], DO_PROJ only
    int tid = threadIdx.x;
    int base = blockIdx.x * FC_NPC;

    // stage Wl^T and [h_in, agg] for 66 nodes
    for (int i = tid; i < 64 * K; i += 512) {
        int j = i / K, k = i - j * K;
        sWT[k * 65 + j] = Wl[i];
    }
    for (int i = tid; i < FC_NPC * IN_D; i += 512) {
        int m = i / IN_D;
        int node = min(base + m, NN - 1);
        scomb[m * K + (i - m * IN_D)] = h_in[(size_t)node * IN_D + (i - m * IN_D)];
    }
    for (int i = tid; i < FC_NPC * 64; i += 512) {
        int m = i >> 6;
        int node = min(base + m, NN - 1);
        scomb[m * K + IN_D + (i & 63)] = g_agg[(size_t)node * 64 + (i & 63)];
    }
    __syncthreads();

    // GEMM1: j = out col, rows r = mg + 8*i (i<=8, r<66)
    {
        int j = tid & 63, mg = tid >> 6;   // mg 0..7
        float acc[9];
        float bj = bl[j];
#pragma unroll
        for (int mm = 0; mm < 9; mm++) acc[mm] = bj;
        if (IN_D == 64) {
            for (int k0 = 0; k0 < 128; k0 += 4) {
                float w0 = sWT[(k0 + 0) * 65 + j];
                float w1 = sWT[(k0 + 1) * 65 + j];
                float w2 = sWT[(k0 + 2) * 65 + j];
                float w3 = sWT[(k0 + 3) * 65 + j];
#pragma unroll
                for (int mm = 0; mm < 9; mm++) {
                    int r = mg + 8 * mm;
                    int rr = min(r, FC_NPC - 1);
                    float4 s = *(const float4*)&scomb[rr * 128 + k0];
                    acc[mm] = fmaf(s.x, w0, acc[mm]);
                    acc[mm] = fmaf(s.y, w1, acc[mm]);
                    acc[mm] = fmaf(s.z, w2, acc[mm]);
                    acc[mm] = fmaf(s.w, w3, acc[mm]);
                }
            }
        } else {
            for (int k = 0; k < K; k++) {
                float wv = sWT[k * 65 + j];
#pragma unroll
                for (int mm = 0; mm < 9; mm++) {
                    int rr = min(mg + 8 * mm, FC_NPC - 1);
                    acc[mm] = fmaf(scomb[rr * K + k], wv, acc[mm]);
                }
            }
        }
#pragma unroll
        for (int mm = 0; mm < 9; mm++) {
            int r = mg + 8 * mm;
            if (r < FC_NPC) {
                float v = fmaxf(acc[mm], 0.f);
                if (DO_PROJ) hbuf[r * 68 + j] = v;
                int node = base + r;
                if (node < NN) h_out[(size_t)node * 64 + j] = v;
            }
        }
    }
    if (DO_PROJ) {
        __syncthreads();   // all reads of sWT/scomb complete

        // stage full W_ihn as W2[256][65] over the GEMM1 region
        float* W2 = csm;
        for (int i = tid; i < 256 * 64; i += 512)
            W2[(i >> 6) * 65 + (i & 63)] = W_ihn[i];
        __syncthreads();

        // GEMM2: thread = (weight row r, m-half of 33), 3 passes of 11 m
        int r = tid & 255;
        int mh = tid >> 8;                 // 0..1 -> rows mh*33 .. mh*33+32
        int dst = gcol(r & 63, r >> 6);
        float bias = b_ihn[r] + b_hhn[r];
#pragma unroll
        for (int p = 0; p < 3; p++) {
            int m0 = mh * 33 + p * 11;
            float pacc[11];
#pragma unroll
            for (int mm = 0; mm < 11; mm++) pacc[mm] = bias;
            for (int k0 = 0; k0 < 64; k0 += 4) {
                float w0 = W2[r * 65 + k0 + 0];
                float w1 = W2[r * 65 + k0 + 1];
                float w2 = W2[r * 65 + k0 + 2];
                float w3 = W2[r * 65 + k0 + 3];
#pragma unroll
                for (int mm = 0; mm < 11; mm++) {
                    float4 h4 = *(const float4*)&hbuf[(m0 + mm) * 68 + k0];
                    pacc[mm] = fmaf(h4.x, w0, pacc[mm]);
                    pacc[mm] = fmaf(h4.y, w1, pacc[mm]);
                    pacc[mm] = fmaf(h4.z, w2, pacc[mm]);
                    pacc[mm] = fmaf(h4.w, w3, pacc[mm]);
                }
            }
#pragma unroll
            for (int mm = 0; mm < 11; mm++) {
                int node = base + m0 + mm;
                if (node < NN) g_Xg[(size_t)node * 256 + dst] = pacc[mm];
            }
        }
    }
}

// ---------------- output head ----------------
__global__ void out_kernel(const float* __restrict__ h, const float* __restrict__ W_out,
                           const float* __restrict__ b_out, float* __restrict__ out) {
    int gw = (blockIdx.x * blockDim.x + threadIdx.x) >> 5;
    int lane = threadIdx.x & 31;
    if (gw >= NN) return;
    float2 hv = *(const float2*)(h + (size_t)gw * 64 + 2 * lane);
    float2 wv = *(const float2*)(W_out + 2 * lane);
    float s = hv.x * wv.x + hv.y * wv.y;
#pragma unroll
    for (int o = 16; o; o >>= 1) s += __shfl_xor_sync(0xFFFFFFFFu, s, o);
    if (lane == 0) out[gw] = s + b_out[0];
}

// ---------------- launch ----------------
extern "C" void kernel_launch(void* const* d_in, const int* in_sizes, int n_in,
                              void* d_out, int out_size) {
    (void)in_sizes; (void)n_in; (void)out_size;
    const float* nf   = (const float*)d_in[0];
    const int*   nbr  = (const int*)d_in[1];
    const float* Wout = (const float*)d_in[20];
    const float* bout = (const float*)d_in[21];
    float* out = (float*)d_out;

    float *hA = nullptr, *hB = nullptr;
    cudaGetSymbolAddress((void**)&hA, g_hA);
    cudaGetSymbolAddress((void**)&hB, g_hB);

    cudaFuncSetAttribute(lstm_mma_kernel, cudaFuncAttributeMaxDynamicSharedMemorySize, LSTM_SMEM);
    cudaFuncSetAttribute(proj_kernel<3>,  cudaFuncAttributeMaxDynamicSharedMemorySize, PROJ_SMEM);
    cudaFuncSetAttribute(fused_combine<3, true>,   cudaFuncAttributeMaxDynamicSharedMemorySize, FUSE_SMEM);
    cudaFuncSetAttribute(fused_combine<64, true>,  cudaFuncAttributeMaxDynamicSharedMemorySize, FUSE_SMEM);
    cudaFuncSetAttribute(fused_combine<64, false>, cudaFuncAttributeMaxDynamicSharedMemorySize, FUSE_SMEM_NP);

    const float* W_hh0 = (const float*)d_in[3];
    const float* Wl0   = (const float*)d_in[6];
    const float* bl0   = (const float*)d_in[7];
    const float* W_ih1 = (const float*)d_in[8];
    const float* W_hh1 = (const float*)d_in[9];
    const float* b_ih1 = (const float*)d_in[10];
    const float* b_hh1 = (const float*)d_in[11];
    const float* Wl1   = (const float*)d_in[12];
    const float* bl1   = (const float*)d_in[13];
    const float* W_ih2 = (const float*)d_in[14];
    const float* W_hh2 = (const float*)d_in[15];
    const float* b_ih2 = (const float*)d_in[16];
    const float* b_hh2 = (const float*)d_in[17];
    const float* Wl2   = (const float*)d_in[18];
    const float* bl2   = (const float*)d_in[19];

    int lstm_grid = (NN + NPC - 1) / NPC;   // 455 <= 456 = 152*3
    int blk64 = (NN + 63) / 64;             // 313 (proj only; small smem, many CTAs/SM)

    sort_kernel<<<NN / 8, 256>>>(nbr);

    // layer 0
    proj_kernel<3><<<blk64, 256, PROJ_SMEM>>>(nf, (const float*)d_in[2],
                                              (const float*)d_in[4], (const float*)d_in[5]);
    lstm_mma_kernel<<<lstm_grid, 128, LSTM_SMEM>>>(W_hh0);
    fused_combine<3, true><<<FC_GRID, 512, FUSE_SMEM>>>(nf, Wl0, bl0, hA, W_ih1, b_ih1, b_hh1);
    // layer 1
    lstm_mma_kernel<<<lstm_grid, 128, LSTM_SMEM>>>(W_hh1);
    fused_combine<64, true><<<FC_GRID, 512, FUSE_SMEM>>>(hA, Wl1, bl1, hB, W_ih2, b_ih2, b_hh2);
    // layer 2
    lstm_mma_kernel<<<lstm_grid, 128, LSTM_SMEM>>>(W_hh2);
    fused_combine<64, false><<<FC_GRID, 512, FUSE_SMEM_NP>>>(hB, Wl2, bl2, hA, nullptr, nullptr, nullptr);

    out_kernel<<<NN / 8, 256>>>(hA, Wout, bout, out);
}